// round 5
// baseline (speedup 1.0000x reference)
#include <cuda_runtime.h>
#include <cstdint>

// LinearInverse_45664092291621
//
// Reference returns y + score(y) = y - y = 0 exactly (score(x) = -x):
// output is zeros((1048576, 2), float32) = 8 MB of zeros.
//
// R1/R2/R4 evidence: STG-kernel fills (two shapes) and the driver memset all
// sit at ~4.5-4.8 us for 8 MB (~1.7 TB/s) -- an SM store/writeback wall that
// is implementation-invariant. This round tries the one untried write path:
// TMA bulk stores (cp.async.bulk shared::cta -> global, async proxy), which
// bypass the SM L1 writeback machinery entirely. 256 CTAs x 32 KB SMEM each
// cover the 8 MB output with one bulk-store instruction per CTA.

#define TPB 128
#define CHUNK 32768  // 32 KB per CTA

__device__ __forceinline__ uint32_t smem_u32(const void* p) {
    uint32_t a;
    asm("{ .reg .u64 t; cvta.to.shared.u64 t, %1; cvt.u32.u64 %0, t; }"
        : "=r"(a) : "l"(p));
    return a;
}

__global__ void __launch_bounds__(TPB) zero_fill_tma(char* __restrict__ out,
                                                     unsigned long long total_bytes) {
    __shared__ __align__(128) char buf[CHUNK];

    // Cooperatively zero SMEM (32 KB / 128 threads = 16 float4 each).
    const float4 z = make_float4(0.0f, 0.0f, 0.0f, 0.0f);
#pragma unroll
    for (int i = 0; i < CHUNK / (TPB * 16); ++i) {
        *reinterpret_cast<float4*>(buf + (i * TPB + threadIdx.x) * 16) = z;
    }
    __syncthreads();
    // Order generic-proxy SMEM writes before async-proxy (bulk copy) reads.
    asm volatile("fence.proxy.async.shared::cta;" ::: "memory");

    unsigned long long off = (unsigned long long)blockIdx.x * CHUNK;
    if (off >= total_bytes) return;

    unsigned long long rem = total_bytes - off;
    unsigned int bytes = rem >= CHUNK ? (unsigned int)CHUNK
                                      : (unsigned int)(rem & ~15ull);  // 16B multiple

    if (threadIdx.x == 0 && bytes > 0) {
        uint32_t src = smem_u32(buf);
        asm volatile(
            "cp.async.bulk.global.shared::cta.bulk_group [%0], [%1], %2;"
            :: "l"(out + off), "r"(src), "r"(bytes)
            : "memory");
        asm volatile("cp.async.bulk.commit_group;" ::: "memory");
        asm volatile("cp.async.bulk.wait_group 0;" ::: "memory");
    }
}

// Guarded scalar fallback for any non-16B-aligned tail (not hit here).
__global__ void __launch_bounds__(TPB) zero_fill_tail(float* __restrict__ out,
                                                      int start, int n) {
    int i = start + blockIdx.x * blockDim.x + threadIdx.x;
    if (i < n) out[i] = 0.0f;
}

extern "C" void kernel_launch(void* const* d_in, const int* in_sizes, int n_in,
                              void* d_out, int out_size) {
    (void)d_in; (void)in_sizes; (void)n_in;

    unsigned long long total_bytes = (unsigned long long)out_size * sizeof(float);
    unsigned int blocks = (unsigned int)((total_bytes + CHUNK - 1) / CHUNK);

    zero_fill_tma<<<blocks, TPB>>>((char*)d_out, total_bytes);

    // Cover a possible non-16B tail (out_size*4 not multiple of 16 => last
    // up-to-15 bytes). For this problem 8 MB divides exactly; never launched.
    unsigned long long covered16 = (total_bytes / 16) * 16;
    if (covered16 < total_bytes) {
        int start = (int)(covered16 / sizeof(float));
        zero_fill_tail<<<1, TPB>>>((float*)d_out, start, out_size);
    }
}

// round 7
// speedup vs baseline: 1.0142x; 1.0142x over previous
#include <cuda_runtime.h>

// LinearInverse_45664092291621
//
// Reference returns y + score(y) = y - y = 0 exactly (score(x) = -x):
// output is zeros((1048576, 2), float32) = 8 MB of zeros.
//
// Measured across four write paths (thin STG grid, fat STG grid, driver
// memset, TMA bulk store): 8 MB fill is pinned at 4.7-5.1 us, L2 ~= 16% of
// the read-side LTS cap (~1000 B/cyc). Sustained L2 *write* throughput is a
// path-independent hardware wall; grid shape is irrelevant. The only
// controllable remainder is graph-replay overhead, which scales with node
// count (2-node graphs cost ~0.3-0.5 us over 1-node).
//
// R6 was an infra failure (container never ran) -- resubmitting unchanged.
//
// This version: ONE kernel node total. Best measured fill shape
// (512 CTAs x 256 threads x 4 float4 stores), with the generic tail folded
// into the same kernel via guards (free at this scale).

#define THREADS 256
#define F4_PER_THREAD 4

__global__ void __launch_bounds__(THREADS) zero_fill(float* __restrict__ out, int n) {
    const float4 z = make_float4(0.0f, 0.0f, 0.0f, 0.0f);
    int n4 = n >> 2;  // full float4s

    int base = (blockIdx.x * THREADS) * F4_PER_THREAD + threadIdx.x;
#pragma unroll
    for (int k = 0; k < F4_PER_THREAD; ++k) {
        int i = base + k * THREADS;
        if (i < n4) {
            reinterpret_cast<float4*>(out)[i] = z;
        }
    }

    // Scalar tail (n % 4 elements), handled by one thread. Never hit for
    // this problem (n = 2097152), but keeps the kernel generic in one node.
    if (blockIdx.x == 0 && threadIdx.x == 0) {
        for (int i = n4 << 2; i < n; ++i) out[i] = 0.0f;
    }
}

extern "C" void kernel_launch(void* const* d_in, const int* in_sizes, int n_in,
                              void* d_out, int out_size) {
    (void)d_in; (void)in_sizes; (void)n_in;

    int n4 = out_size >> 2;
    int per_block = THREADS * F4_PER_THREAD;
    int blocks = (n4 + per_block - 1) / per_block;
    if (blocks < 1) blocks = 1;

    zero_fill<<<blocks, THREADS>>>((float*)d_out, out_size);
}

// round 8
// speedup vs baseline: 1.1088x; 1.0933x over previous
#include <cuda_runtime.h>

// LinearInverse_45664092291621
//
// Reference returns y + score(y) = y - y = 0 exactly (score(x) = -x):
// output is zeros((1048576, 2), float32) = 8 MB of zeros.
//
// Exhaustive search of write paths (thin/fat STG grids, TMA bulk store,
// driver memset) and graph shapes (1 vs 2 nodes) shows every 8 MB fill costs
// 4.7-5.1 us of kernel time -- consistent with fixed kernel overhead
// (T_ovh ~= 5000 cyc ~= 2.7 us) plus ~1-2 us of L2-resident store traffic,
// not a tunable bandwidth limit. Totals spread 6.18-6.85 us with ~0.3 us
// bench noise; the single driver-memset node measured best (6.18 us).
//
// Final configuration: one graph memset node. Graph-capturable
// (memset node), allocation-free, deterministic; zeros are bytewise zero so
// one byte-memset is exact for any out_size.

extern "C" void kernel_launch(void* const* d_in, const int* in_sizes, int n_in,
                              void* d_out, int out_size) {
    (void)d_in; (void)in_sizes; (void)n_in;
    cudaMemsetAsync(d_out, 0, (size_t)out_size * sizeof(float), 0);
}